// round 14
// baseline (speedup 1.0000x reference)
#include <cuda_runtime.h>
#include <cuda_bf16.h>

// Problem constants
#define B_DIM 128
#define L_DIM 1024
#define D_DIM 128
#define DVF   32          // D/4 float4 groups (full row)
#define DT    4           // float4 groups per D-tile (D split 8 ways)
#define TS    128         // starts per chunk
#define NPOS  159         // TS + 31 halo
#define NS4   156         // TS + 28 sliding-4-sum rows
#define NTH   256
#define GRID  1184        // 148 SMs x 8 CTAs: one persistent wave
#define NCH   8192        // 8 L-chunks x 8 D-tiles x 128 batches

// Output row offsets for window sizes 4, 8, 16, 32
#define OFF4  0
#define OFF8  1021
#define OFF16 2038
#define OFF32 3047
#define ROWS  4040

// Shared memory: double-buffered s4 / inv / msk
#define S4SZ  (NS4 * DT)                 // float4 per buffer (624)
#define SMEM_FLOATS (2 * S4SZ * 4 + 2 * 4 * TS + 2 * 160)
#define SMEM_BYTES  (SMEM_FLOATS * 4)

__device__ __forceinline__ float4 add4(float4 a, float4 b) {
    return make_float4(a.x + b.x, a.y + b.y, a.z + b.z, a.w + b.w);
}
__device__ __forceinline__ float4 scl4(float4 a, float s) {
    return make_float4(a.x * s, a.y * s, a.z * s, a.w * s);
}
__device__ __forceinline__ void decode(int t, int& b, int& dbase, int& s0) {
    b     = t & 127;
    dbase = ((t >> 7) & 7) * DT;
    s0    = (t >> 10) * TS;
}

extern __shared__ float smem_raw[];

__global__ __launch_bounds__(NTH, 8)
void msse_kernel(const float* __restrict__ x,
                 const int* __restrict__ mask,
                 float* __restrict__ out)
{
    const int tid = threadIdx.x;
    const int t0  = blockIdx.x;

    float4* s4buf  = reinterpret_cast<float4*>(smem_raw);           // [2][S4SZ]
    float*  invbuf = reinterpret_cast<float*>(s4buf + 2 * S4SZ);    // [2][4*TS]
    int*    mskbuf = reinterpret_cast<int*>(invbuf + 2 * 4 * TS);   // [2][160]

    // ---- prologue: mask for first chunk into slot 0 ----
    {
        int b, dbase, s0;
        decode(t0, b, dbase, s0);
        if (tid < NPOS) {
            int g = s0 + tid;
            mskbuf[tid] = (g < L_DIM) ? mask[(size_t)b * L_DIM + g] : 0;
        }
    }
    __syncthreads();

    int prev_t = -1;
    int s = 0;

    for (int t = t0; t < NCH; t += GRID) {
        // ========== drain: outputs for prev chunk (slot s^1) =============
        if (prev_t >= 0) {
            int b, dbase, s0;
            decode(prev_t, b, dbase, s0);
            const float4* s4  = s4buf + (s ^ 1) * S4SZ;
            const float*  inv = invbuf + (s ^ 1) * 4 * TS;
            float4* outb = reinterpret_cast<float4*>(out + (size_t)b * ROWS * D_DIM);

            const int q   = tid & 3;
            const int idx = tid >> 2;       // 0..63
            const int jm  = idx & 3;
            const int kk  = idx >> 2;       // 0..15
            const int j0  = jm + 8 * kk;    // first start of pair
            const int j1  = j0 + 4;
            const int gi0 = s0 + j0;
            const int gi1 = s0 + j1;
            const int oq  = dbase + q;
            const float4* sp = s4 + j0 * DT + q;

            float4 a    = sp[0];
            float4 accA = a;
            if (gi0 <= L_DIM - 4)
                __stcs(&outb[(OFF4 + gi0) * DVF + oq], scl4(a, inv[0 * TS + j0]));
            a = sp[4 * DT];
            float4 accB = a;
            if (gi1 <= L_DIM - 4)
                __stcs(&outb[(OFF4 + gi1) * DVF + oq], scl4(a, inv[0 * TS + j1]));
            accA = add4(accA, a);
            if (gi0 <= L_DIM - 8)
                __stcs(&outb[(OFF8 + gi0) * DVF + oq], scl4(accA, inv[1 * TS + j0]));
            a = sp[8 * DT];
            accB = add4(accB, a);
            if (gi1 <= L_DIM - 8)
                __stcs(&outb[(OFF8 + gi1) * DVF + oq], scl4(accB, inv[1 * TS + j1]));
            accA = add4(accA, a);
            a = sp[12 * DT];
            accA = add4(accA, a);
            if (gi0 <= L_DIM - 16)
                __stcs(&outb[(OFF16 + gi0) * DVF + oq], scl4(accA, inv[2 * TS + j0]));
            accB = add4(accB, a);
            a = sp[16 * DT];
            accB = add4(accB, a);
            if (gi1 <= L_DIM - 16)
                __stcs(&outb[(OFF16 + gi1) * DVF + oq], scl4(accB, inv[2 * TS + j1]));
            accA = add4(accA, a);
            a = sp[20 * DT];
            accA = add4(accA, a);
            accB = add4(accB, a);
            a = sp[24 * DT];
            accA = add4(accA, a);
            accB = add4(accB, a);
            a = sp[28 * DT];
            accA = add4(accA, a);
            if (gi0 <= L_DIM - 32)
                __stcs(&outb[(OFF32 + gi0) * DVF + oq], scl4(accA, inv[3 * TS + j0]));
            accB = add4(accB, a);
            a = sp[32 * DT];
            accB = add4(accB, a);
            if (gi1 <= L_DIM - 32)
                __stcs(&outb[(OFF32 + gi1) * DVF + oq], scl4(accB, inv[3 * TS + j1]));
        }

        // ========== build: s4 (threads 0-155, rolling) + inv (160-223) ====
        {
            int b, dbase, s0;
            decode(t, b, dbase, s0);
            const int* msk = mskbuf + s * 160;
            float4*    s4  = s4buf + s * S4SZ;
            float*     inv = invbuf + s * 4 * TS;

            if (tid < 156) {
                // run r covers s4 rows [4r, 4r+4); needs x rows [4r, 4r+7)
                const int r  = tid >> 2;      // 0..38
                const int q  = tid & 3;
                const int p0 = r * 4;
                const float4* xrow = reinterpret_cast<const float4*>(
                    x + (size_t)b * L_DIM * D_DIM);
                const float4* base = xrow + (size_t)(s0 + p0) * DVF + dbase + q;
                const float4 fz = make_float4(0.f, 0.f, 0.f, 0.f);

                float4 w0 = msk[p0]     ? __ldg(base)           : fz;
                float4 w1 = msk[p0 + 1] ? __ldg(base + DVF)     : fz;
                float4 w2 = msk[p0 + 2] ? __ldg(base + 2 * DVF) : fz;
                #pragma unroll
                for (int i = 0; i < 4; i++) {
                    float4 w3 = msk[p0 + i + 3] ? __ldg(base + (i + 3) * DVF) : fz;
                    s4[(p0 + i) * DT + q] = add4(add4(w0, w1), add4(w2, w3));
                    w0 = w1; w1 = w2; w2 = w3;
                }
            } else if (tid >= 160 && tid < 224) {
                #pragma unroll
                for (int h = 0; h < 2; h++) {
                    const int j = (tid - 160) + h * 64;   // 0..127
                    int c = 0;
                    #pragma unroll
                    for (int k = 0; k < 4; k++)  c += msk[j + k];
                    int c4 = c;
                    #pragma unroll
                    for (int k = 4; k < 8; k++)  c += msk[j + k];
                    int c8 = c;
                    #pragma unroll
                    for (int k = 8; k < 16; k++) c += msk[j + k];
                    int c16 = c;
                    #pragma unroll
                    for (int k = 16; k < 32; k++) c += msk[j + k];
                    int c32 = c;
                    inv[0 * TS + j] = 1.0f / (float)(c4  > 1 ? c4  : 1);
                    inv[1 * TS + j] = 1.0f / (float)(c8  > 1 ? c8  : 1);
                    inv[2 * TS + j] = 1.0f / (float)(c16 > 1 ? c16 : 1);
                    inv[3 * TS + j] = 1.0f / (float)(c32 > 1 ? c32 : 1);
                }
            }
        }

        // ========== prefetch: mask for chunk t+GRID into slot s^1 =========
        if (t + GRID < NCH && tid < NPOS) {
            int b, dbase, s0;
            decode(t + GRID, b, dbase, s0);
            int g = s0 + tid;
            mskbuf[(s ^ 1) * 160 + tid] =
                (g < L_DIM) ? mask[(size_t)b * L_DIM + g] : 0;
        }

        __syncthreads();
        prev_t = t;
        s ^= 1;
    }

    // ========== epilogue: drain last chunk (slot s^1) =====================
    if (prev_t >= 0) {
        int b, dbase, s0;
        decode(prev_t, b, dbase, s0);
        const float4* s4  = s4buf + (s ^ 1) * S4SZ;
        const float*  inv = invbuf + (s ^ 1) * 4 * TS;
        float4* outb = reinterpret_cast<float4*>(out + (size_t)b * ROWS * D_DIM);

        const int q   = tid & 3;
        const int idx = tid >> 2;
        const int jm  = idx & 3;
        const int kk  = idx >> 2;
        const int j0  = jm + 8 * kk;
        const int j1  = j0 + 4;
        const int gi0 = s0 + j0;
        const int gi1 = s0 + j1;
        const int oq  = dbase + q;
        const float4* sp = s4 + j0 * DT + q;

        float4 a    = sp[0];
        float4 accA = a;
        if (gi0 <= L_DIM - 4)
            __stcs(&outb[(OFF4 + gi0) * DVF + oq], scl4(a, inv[0 * TS + j0]));
        a = sp[4 * DT];
        float4 accB = a;
        if (gi1 <= L_DIM - 4)
            __stcs(&outb[(OFF4 + gi1) * DVF + oq], scl4(a, inv[0 * TS + j1]));
        accA = add4(accA, a);
        if (gi0 <= L_DIM - 8)
            __stcs(&outb[(OFF8 + gi0) * DVF + oq], scl4(accA, inv[1 * TS + j0]));
        a = sp[8 * DT];
        accB = add4(accB, a);
        if (gi1 <= L_DIM - 8)
            __stcs(&outb[(OFF8 + gi1) * DVF + oq], scl4(accB, inv[1 * TS + j1]));
        accA = add4(accA, a);
        a = sp[12 * DT];
        accA = add4(accA, a);
        if (gi0 <= L_DIM - 16)
            __stcs(&outb[(OFF16 + gi0) * DVF + oq], scl4(accA, inv[2 * TS + j0]));
        accB = add4(accB, a);
        a = sp[16 * DT];
        accB = add4(accB, a);
        if (gi1 <= L_DIM - 16)
            __stcs(&outb[(OFF16 + gi1) * DVF + oq], scl4(accB, inv[2 * TS + j1]));
        accA = add4(accA, a);
        a = sp[20 * DT];
        accA = add4(accA, a);
        accB = add4(accB, a);
        a = sp[24 * DT];
        accA = add4(accA, a);
        accB = add4(accB, a);
        a = sp[28 * DT];
        accA = add4(accA, a);
        if (gi0 <= L_DIM - 32)
            __stcs(&outb[(OFF32 + gi0) * DVF + oq], scl4(accA, inv[3 * TS + j0]));
        accB = add4(accB, a);
        a = sp[32 * DT];
        accB = add4(accB, a);
        if (gi1 <= L_DIM - 32)
            __stcs(&outb[(OFF32 + gi1) * DVF + oq], scl4(accB, inv[3 * TS + j1]));
    }
}

extern "C" void kernel_launch(void* const* d_in, const int* in_sizes, int n_in,
                              void* d_out, int out_size)
{
    const float* x    = (const float*)d_in[0];
    const int*   mask = (const int*)d_in[1];
    float*       out  = (float*)d_out;

    cudaFuncSetAttribute(msse_kernel,
                         cudaFuncAttributeMaxDynamicSharedMemorySize, SMEM_BYTES);

    msse_kernel<<<GRID, NTH, SMEM_BYTES>>>(x, mask, out);
}

// round 15
// speedup vs baseline: 1.0344x; 1.0344x over previous
#include <cuda_runtime.h>
#include <cuda_bf16.h>

// Problem constants
#define B_DIM 128
#define L_DIM 1024
#define D_DIM 128
#define DVF   32          // D/4 float4 groups (full row)
#define DT    8           // float4 groups per D-tile (128B rows — keep coalescing)
#define TS    64          // starts per chunk
#define NPOS  96          // TS + 31 halo (padded to 96)
#define NS4   92          // TS + 28 sliding-4-sum rows
#define NTH   256
#define GRID  1036        // 148 SMs x 7 CTAs: one persistent wave
#define NCH   8192        // 16 L-chunks x 4 D-tiles x 128 batches

// Output row offsets for window sizes 4, 8, 16, 32
#define OFF4  0
#define OFF8  1021
#define OFF16 2038
#define OFF32 3047
#define ROWS  4040

// Shared memory: double-buffered s4 / inv / msk
#define S4SZ  (NS4 * DT)                 // float4 per buffer
#define SMEM_FLOATS (2 * S4SZ * 4 + 2 * 4 * TS + 2 * NPOS)
#define SMEM_BYTES  (SMEM_FLOATS * 4)

__device__ __forceinline__ float4 add4(float4 a, float4 b) {
    return make_float4(a.x + b.x, a.y + b.y, a.z + b.z, a.w + b.w);
}
__device__ __forceinline__ float4 scl4(float4 a, float s) {
    return make_float4(a.x * s, a.y * s, a.z * s, a.w * s);
}
__device__ __forceinline__ void decode(int t, int& b, int& dbase, int& s0) {
    b     = t & 127;
    dbase = ((t >> 7) & 3) * DT;
    s0    = (t >> 9) * TS;
}

extern __shared__ float smem_raw[];

__global__ __launch_bounds__(NTH, 7)
void msse_kernel(const float* __restrict__ x,
                 const int* __restrict__ mask,
                 float* __restrict__ out)
{
    const int tid = threadIdx.x;
    const int t0  = blockIdx.x;

    float4* s4buf  = reinterpret_cast<float4*>(smem_raw);           // [2][S4SZ]
    float*  invbuf = reinterpret_cast<float*>(s4buf + 2 * S4SZ);    // [2][4*TS]
    int*    mskbuf = reinterpret_cast<int*>(invbuf + 2 * 4 * TS);   // [2][NPOS]

    // ---- prologue: mask for first chunk into slot 0 ----
    {
        int b, dbase, s0;
        decode(t0, b, dbase, s0);
        if (tid < NPOS) {
            int g = s0 + tid;
            mskbuf[tid] = (g < L_DIM) ? mask[(size_t)b * L_DIM + g] : 0;
        }
    }
    __syncthreads();

    int prev_t = -1;
    int s = 0;

    for (int t = t0; t < NCH; t += GRID) {
        // ---- chunk-t coordinates (build target, slot s) ----
        int bb, dbb, sb0;
        decode(t, bb, dbb, sb0);
        const int* mskc = mskbuf + s * NPOS;

        // ===== early-issue: first 3 build loads + mask prefetch LDG =======
        // Their ~L2/DRAM latency is hidden under the drain below.
        const int br = tid >> 3;          // 0..31 (build run id; <23 active)
        const int bq = tid & 7;
        const int bp0 = br * 4;
        const bool bactive = (tid < 184);
        const float4 fz = make_float4(0.f, 0.f, 0.f, 0.f);
        const float4* bbase = reinterpret_cast<const float4*>(
            x + (size_t)bb * L_DIM * D_DIM) + (size_t)(sb0 + bp0) * DVF + dbb + bq;

        float4 w0 = fz, w1 = fz, w2 = fz;
        if (bactive) {
            if (mskc[bp0])     w0 = __ldg(bbase);
            if (mskc[bp0 + 1]) w1 = __ldg(bbase + DVF);
            if (mskc[bp0 + 2]) w2 = __ldg(bbase + 2 * DVF);
        }

        int mpre = 0;
        const bool do_pre = (t + GRID < NCH) && (tid < NPOS);
        if (do_pre) {
            int b2, db2, s02;
            decode(t + GRID, b2, db2, s02);
            int g = s02 + tid;
            mpre = (g < L_DIM) ? __ldg(mask + (size_t)b2 * L_DIM + g) : 0;
        }

        // ========== drain: outputs for prev chunk (slot s^1) =============
        if (prev_t >= 0) {
            int b, dbase, s0;
            decode(prev_t, b, dbase, s0);
            const float4* s4  = s4buf + (s ^ 1) * S4SZ;
            const float*  inv = invbuf + (s ^ 1) * 4 * TS;
            float4* outb = reinterpret_cast<float4*>(out + (size_t)b * ROWS * D_DIM);

            const int q   = tid & 7;
            const int idx = tid >> 3;       // 0..31
            const int jm  = idx & 3;
            const int kk  = idx >> 2;       // 0..7
            const int j0  = jm + 8 * kk;    // first start of pair
            const int j1  = j0 + 4;
            const int gi0 = s0 + j0;
            const int gi1 = s0 + j1;
            const int oq  = dbase + q;
            const float4* sp = s4 + j0 * DT + q;

            float4 a    = sp[0];
            float4 accA = a;
            if (gi0 <= L_DIM - 4)
                __stcs(&outb[(OFF4 + gi0) * DVF + oq], scl4(a, inv[0 * TS + j0]));
            a = sp[4 * DT];
            float4 accB = a;
            if (gi1 <= L_DIM - 4)
                __stcs(&outb[(OFF4 + gi1) * DVF + oq], scl4(a, inv[0 * TS + j1]));
            accA = add4(accA, a);
            if (gi0 <= L_DIM - 8)
                __stcs(&outb[(OFF8 + gi0) * DVF + oq], scl4(accA, inv[1 * TS + j0]));
            a = sp[8 * DT];
            accB = add4(accB, a);
            if (gi1 <= L_DIM - 8)
                __stcs(&outb[(OFF8 + gi1) * DVF + oq], scl4(accB, inv[1 * TS + j1]));
            accA = add4(accA, a);
            a = sp[12 * DT];
            accA = add4(accA, a);
            if (gi0 <= L_DIM - 16)
                __stcs(&outb[(OFF16 + gi0) * DVF + oq], scl4(accA, inv[2 * TS + j0]));
            accB = add4(accB, a);
            a = sp[16 * DT];
            accB = add4(accB, a);
            if (gi1 <= L_DIM - 16)
                __stcs(&outb[(OFF16 + gi1) * DVF + oq], scl4(accB, inv[2 * TS + j1]));
            accA = add4(accA, a);
            a = sp[20 * DT];
            accA = add4(accA, a);
            accB = add4(accB, a);
            a = sp[24 * DT];
            accA = add4(accA, a);
            accB = add4(accB, a);
            a = sp[28 * DT];
            accA = add4(accA, a);
            if (gi0 <= L_DIM - 32)
                __stcs(&outb[(OFF32 + gi0) * DVF + oq], scl4(accA, inv[3 * TS + j0]));
            accB = add4(accB, a);
            a = sp[32 * DT];
            accB = add4(accB, a);
            if (gi1 <= L_DIM - 32)
                __stcs(&outb[(OFF32 + gi1) * DVF + oq], scl4(accB, inv[3 * TS + j1]));
        }

        // ========== build finish: s4 rolling (0-183) + inv (192-255) ======
        {
            float4* s4  = s4buf + s * S4SZ;
            float*  inv = invbuf + s * 4 * TS;

            if (bactive) {
                #pragma unroll
                for (int i = 0; i < 4; i++) {
                    float4 w3 = mskc[bp0 + i + 3] ? __ldg(bbase + (i + 3) * DVF) : fz;
                    s4[(bp0 + i) * DT + bq] = add4(add4(w0, w1), add4(w2, w3));
                    w0 = w1; w1 = w2; w2 = w3;
                }
            } else if (tid >= 192) {
                const int j = tid - 192;      // 0..63
                int c = 0;
                #pragma unroll
                for (int k = 0; k < 4; k++)  c += mskc[j + k];
                int c4 = c;
                #pragma unroll
                for (int k = 4; k < 8; k++)  c += mskc[j + k];
                int c8 = c;
                #pragma unroll
                for (int k = 8; k < 16; k++) c += mskc[j + k];
                int c16 = c;
                #pragma unroll
                for (int k = 16; k < 32; k++) c += mskc[j + k];
                int c32 = c;
                inv[0 * TS + j] = 1.0f / (float)(c4  > 1 ? c4  : 1);
                inv[1 * TS + j] = 1.0f / (float)(c8  > 1 ? c8  : 1);
                inv[2 * TS + j] = 1.0f / (float)(c16 > 1 ? c16 : 1);
                inv[3 * TS + j] = 1.0f / (float)(c32 > 1 ? c32 : 1);
            }
        }

        // ---- store prefetched mask into slot s^1 ----
        if (do_pre) mskbuf[(s ^ 1) * NPOS + tid] = mpre;

        __syncthreads();
        prev_t = t;
        s ^= 1;
    }

    // ========== epilogue: drain last chunk (slot s^1) =====================
    if (prev_t >= 0) {
        int b, dbase, s0;
        decode(prev_t, b, dbase, s0);
        const float4* s4  = s4buf + (s ^ 1) * S4SZ;
        const float*  inv = invbuf + (s ^ 1) * 4 * TS;
        float4* outb = reinterpret_cast<float4*>(out + (size_t)b * ROWS * D_DIM);

        const int q   = tid & 7;
        const int idx = tid >> 3;
        const int jm  = idx & 3;
        const int kk  = idx >> 2;
        const int j0  = jm + 8 * kk;
        const int j1  = j0 + 4;
        const int gi0 = s0 + j0;
        const int gi1 = s0 + j1;
        const int oq  = dbase + q;
        const float4* sp = s4 + j0 * DT + q;

        float4 a    = sp[0];
        float4 accA = a;
        if (gi0 <= L_DIM - 4)
            __stcs(&outb[(OFF4 + gi0) * DVF + oq], scl4(a, inv[0 * TS + j0]));
        a = sp[4 * DT];
        float4 accB = a;
        if (gi1 <= L_DIM - 4)
            __stcs(&outb[(OFF4 + gi1) * DVF + oq], scl4(a, inv[0 * TS + j1]));
        accA = add4(accA, a);
        if (gi0 <= L_DIM - 8)
            __stcs(&outb[(OFF8 + gi0) * DVF + oq], scl4(accA, inv[1 * TS + j0]));
        a = sp[8 * DT];
        accB = add4(accB, a);
        if (gi1 <= L_DIM - 8)
            __stcs(&outb[(OFF8 + gi1) * DVF + oq], scl4(accB, inv[1 * TS + j1]));
        accA = add4(accA, a);
        a = sp[12 * DT];
        accA = add4(accA, a);
        if (gi0 <= L_DIM - 16)
            __stcs(&outb[(OFF16 + gi0) * DVF + oq], scl4(accA, inv[2 * TS + j0]));
        accB = add4(accB, a);
        a = sp[16 * DT];
        accB = add4(accB, a);
        if (gi1 <= L_DIM - 16)
            __stcs(&outb[(OFF16 + gi1) * DVF + oq], scl4(accB, inv[2 * TS + j1]));
        accA = add4(accA, a);
        a = sp[20 * DT];
        accA = add4(accA, a);
        accB = add4(accB, a);
        a = sp[24 * DT];
        accA = add4(accA, a);
        accB = add4(accB, a);
        a = sp[28 * DT];
        accA = add4(accA, a);
        if (gi0 <= L_DIM - 32)
            __stcs(&outb[(OFF32 + gi0) * DVF + oq], scl4(accA, inv[3 * TS + j0]));
        accB = add4(accB, a);
        a = sp[32 * DT];
        accB = add4(accB, a);
        if (gi1 <= L_DIM - 32)
            __stcs(&outb[(OFF32 + gi1) * DVF + oq], scl4(accB, inv[3 * TS + j1]));
    }
}

extern "C" void kernel_launch(void* const* d_in, const int* in_sizes, int n_in,
                              void* d_out, int out_size)
{
    const float* x    = (const float*)d_in[0];
    const int*   mask = (const int*)d_in[1];
    float*       out  = (float*)d_out;

    cudaFuncSetAttribute(msse_kernel,
                         cudaFuncAttributeMaxDynamicSharedMemorySize, SMEM_BYTES);

    msse_kernel<<<GRID, NTH, SMEM_BYTES>>>(x, mask, out);
}

// round 16
// speedup vs baseline: 1.1386x; 1.1007x over previous
#include <cuda_runtime.h>
#include <cuda_bf16.h>

// Problem constants
#define B_DIM 128
#define L_DIM 1024
#define D_DIM 128
#define DVF   32          // D/4 float4 groups (full row)
#define DT    8           // float4 groups per D-tile (128B rows — keep coalescing)
#define TS    128         // starts per chunk (lower halo tax: 156/128 = 1.22)
#define NPOS  159         // TS + 31 halo
#define NS4   156         // TS + 28 sliding-4-sum rows
#define NTH   512
#define GRID  592         // 148 SMs x 4 CTAs: one persistent wave
#define NCH   4096        // 8 L-chunks x 4 D-tiles x 128 batches

// Output row offsets for window sizes 4, 8, 16, 32
#define OFF4  0
#define OFF8  1021
#define OFF16 2038
#define OFF32 3047
#define ROWS  4040

// Shared memory: double-buffered s4 / inv / msk
#define S4SZ  (NS4 * DT)                 // float4 per buffer (1248)
#define SMEM_FLOATS (2 * S4SZ * 4 + 2 * 4 * TS + 2 * 160)
#define SMEM_BYTES  (SMEM_FLOATS * 4)    // 45312 B -> 4 CTAs/SM

__device__ __forceinline__ float4 add4(float4 a, float4 b) {
    return make_float4(a.x + b.x, a.y + b.y, a.z + b.z, a.w + b.w);
}
__device__ __forceinline__ float4 scl4(float4 a, float s) {
    return make_float4(a.x * s, a.y * s, a.z * s, a.w * s);
}
__device__ __forceinline__ void decode(int t, int& b, int& dbase, int& s0) {
    b     = t & 127;
    dbase = ((t >> 7) & 3) * DT;
    s0    = (t >> 9) * TS;
}

extern __shared__ float smem_raw[];

__global__ __launch_bounds__(NTH, 4)
void msse_kernel(const float* __restrict__ x,
                 const int* __restrict__ mask,
                 float* __restrict__ out)
{
    const int tid = threadIdx.x;
    const int t0  = blockIdx.x;

    float4* s4buf  = reinterpret_cast<float4*>(smem_raw);           // [2][S4SZ]
    float*  invbuf = reinterpret_cast<float*>(s4buf + 2 * S4SZ);    // [2][4*TS]
    int*    mskbuf = reinterpret_cast<int*>(invbuf + 2 * 4 * TS);   // [2][160]

    // ---- prologue: mask for first chunk into slot 0 ----
    {
        int b, dbase, s0;
        decode(t0, b, dbase, s0);
        if (tid < NPOS) {
            int g = s0 + tid;
            mskbuf[tid] = (g < L_DIM) ? mask[(size_t)b * L_DIM + g] : 0;
        }
    }
    __syncthreads();

    int prev_t = -1;
    int s = 0;

    for (int t = t0; t < NCH; t += GRID) {
        // ========== drain: outputs for prev chunk (slot s^1) =============
        if (prev_t >= 0) {
            int b, dbase, s0;
            decode(prev_t, b, dbase, s0);
            const float4* s4  = s4buf + (s ^ 1) * S4SZ;
            const float*  inv = invbuf + (s ^ 1) * 4 * TS;
            float4* outb = reinterpret_cast<float4*>(out + (size_t)b * ROWS * D_DIM);

            const int q   = tid & 7;
            const int idx = tid >> 3;       // 0..63
            const int jm  = idx & 3;
            const int kk  = idx >> 2;       // 0..15
            const int j0  = jm + 8 * kk;    // first start of pair (0..123)
            const int j1  = j0 + 4;
            const int gi0 = s0 + j0;
            const int gi1 = s0 + j1;
            const int oq  = dbase + q;
            const float4* sp = s4 + j0 * DT + q;

            float4 a    = sp[0];
            float4 accA = a;
            if (gi0 <= L_DIM - 4)
                __stcs(&outb[(OFF4 + gi0) * DVF + oq], scl4(a, inv[0 * TS + j0]));
            a = sp[4 * DT];
            float4 accB = a;
            if (gi1 <= L_DIM - 4)
                __stcs(&outb[(OFF4 + gi1) * DVF + oq], scl4(a, inv[0 * TS + j1]));
            accA = add4(accA, a);
            if (gi0 <= L_DIM - 8)
                __stcs(&outb[(OFF8 + gi0) * DVF + oq], scl4(accA, inv[1 * TS + j0]));
            a = sp[8 * DT];
            accB = add4(accB, a);
            if (gi1 <= L_DIM - 8)
                __stcs(&outb[(OFF8 + gi1) * DVF + oq], scl4(accB, inv[1 * TS + j1]));
            accA = add4(accA, a);
            a = sp[12 * DT];
            accA = add4(accA, a);
            if (gi0 <= L_DIM - 16)
                __stcs(&outb[(OFF16 + gi0) * DVF + oq], scl4(accA, inv[2 * TS + j0]));
            accB = add4(accB, a);
            a = sp[16 * DT];
            accB = add4(accB, a);
            if (gi1 <= L_DIM - 16)
                __stcs(&outb[(OFF16 + gi1) * DVF + oq], scl4(accB, inv[2 * TS + j1]));
            accA = add4(accA, a);
            a = sp[20 * DT];
            accA = add4(accA, a);
            accB = add4(accB, a);
            a = sp[24 * DT];
            accA = add4(accA, a);
            accB = add4(accB, a);
            a = sp[28 * DT];
            accA = add4(accA, a);
            if (gi0 <= L_DIM - 32)
                __stcs(&outb[(OFF32 + gi0) * DVF + oq], scl4(accA, inv[3 * TS + j0]));
            accB = add4(accB, a);
            a = sp[32 * DT];
            accB = add4(accB, a);
            if (gi1 <= L_DIM - 32)
                __stcs(&outb[(OFF32 + gi1) * DVF + oq], scl4(accB, inv[3 * TS + j1]));
        }

        // ========== build: s4 (threads 0-311, rolling) + inv (320-447) ====
        {
            int b, dbase, s0;
            decode(t, b, dbase, s0);
            const int* msk = mskbuf + s * 160;
            float4*    s4  = s4buf + s * S4SZ;
            float*     inv = invbuf + s * 4 * TS;

            if (tid < 312) {
                // run r covers s4 rows [4r, 4r+4); needs x rows [4r, 4r+7)
                const int r  = tid >> 3;      // 0..38
                const int q  = tid & 7;
                const int p0 = r * 4;
                const float4* xrow = reinterpret_cast<const float4*>(
                    x + (size_t)b * L_DIM * D_DIM);
                const float4* base = xrow + (size_t)(s0 + p0) * DVF + dbase + q;
                const float4 fz = make_float4(0.f, 0.f, 0.f, 0.f);

                float4 w0 = msk[p0]     ? __ldg(base)           : fz;
                float4 w1 = msk[p0 + 1] ? __ldg(base + DVF)     : fz;
                float4 w2 = msk[p0 + 2] ? __ldg(base + 2 * DVF) : fz;
                #pragma unroll
                for (int i = 0; i < 4; i++) {
                    float4 w3 = msk[p0 + i + 3] ? __ldg(base + (i + 3) * DVF) : fz;
                    s4[(p0 + i) * DT + q] = add4(add4(w0, w1), add4(w2, w3));
                    w0 = w1; w1 = w2; w2 = w3;
                }
            } else if (tid >= 320 && tid < 448) {
                const int j = tid - 320;      // 0..127
                int c = 0;
                #pragma unroll
                for (int k = 0; k < 4; k++)  c += msk[j + k];
                int c4 = c;
                #pragma unroll
                for (int k = 4; k < 8; k++)  c += msk[j + k];
                int c8 = c;
                #pragma unroll
                for (int k = 8; k < 16; k++) c += msk[j + k];
                int c16 = c;
                #pragma unroll
                for (int k = 16; k < 32; k++) c += msk[j + k];
                int c32 = c;
                inv[0 * TS + j] = 1.0f / (float)(c4  > 1 ? c4  : 1);
                inv[1 * TS + j] = 1.0f / (float)(c8  > 1 ? c8  : 1);
                inv[2 * TS + j] = 1.0f / (float)(c16 > 1 ? c16 : 1);
                inv[3 * TS + j] = 1.0f / (float)(c32 > 1 ? c32 : 1);
            }
        }

        // ========== prefetch: mask for chunk t+GRID into slot s^1 =========
        if (t + GRID < NCH && tid < NPOS) {
            int b, dbase, s0;
            decode(t + GRID, b, dbase, s0);
            int g = s0 + tid;
            mskbuf[(s ^ 1) * 160 + tid] =
                (g < L_DIM) ? mask[(size_t)b * L_DIM + g] : 0;
        }

        __syncthreads();
        prev_t = t;
        s ^= 1;
    }

    // ========== epilogue: drain last chunk (slot s^1) =====================
    if (prev_t >= 0) {
        int b, dbase, s0;
        decode(prev_t, b, dbase, s0);
        const float4* s4  = s4buf + (s ^ 1) * S4SZ;
        const float*  inv = invbuf + (s ^ 1) * 4 * TS;
        float4* outb = reinterpret_cast<float4*>(out + (size_t)b * ROWS * D_DIM);

        const int q   = tid & 7;
        const int idx = tid >> 3;
        const int jm  = idx & 3;
        const int kk  = idx >> 2;
        const int j0  = jm + 8 * kk;
        const int j1  = j0 + 4;
        const int gi0 = s0 + j0;
        const int gi1 = s0 + j1;
        const int oq  = dbase + q;
        const float4* sp = s4 + j0 * DT + q;

        float4 a    = sp[0];
        float4 accA = a;
        if (gi0 <= L_DIM - 4)
            __stcs(&outb[(OFF4 + gi0) * DVF + oq], scl4(a, inv[0 * TS + j0]));
        a = sp[4 * DT];
        float4 accB = a;
        if (gi1 <= L_DIM - 4)
            __stcs(&outb[(OFF4 + gi1) * DVF + oq], scl4(a, inv[0 * TS + j1]));
        accA = add4(accA, a);
        if (gi0 <= L_DIM - 8)
            __stcs(&outb[(OFF8 + gi0) * DVF + oq], scl4(accA, inv[1 * TS + j0]));
        a = sp[8 * DT];
        accB = add4(accB, a);
        if (gi1 <= L_DIM - 8)
            __stcs(&outb[(OFF8 + gi1) * DVF + oq], scl4(accB, inv[1 * TS + j1]));
        accA = add4(accA, a);
        a = sp[12 * DT];
        accA = add4(accA, a);
        if (gi0 <= L_DIM - 16)
            __stcs(&outb[(OFF16 + gi0) * DVF + oq], scl4(accA, inv[2 * TS + j0]));
        accB = add4(accB, a);
        a = sp[16 * DT];
        accB = add4(accB, a);
        if (gi1 <= L_DIM - 16)
            __stcs(&outb[(OFF16 + gi1) * DVF + oq], scl4(accB, inv[2 * TS + j1]));
        accA = add4(accA, a);
        a = sp[20 * DT];
        accA = add4(accA, a);
        accB = add4(accB, a);
        a = sp[24 * DT];
        accA = add4(accA, a);
        accB = add4(accB, a);
        a = sp[28 * DT];
        accA = add4(accA, a);
        if (gi0 <= L_DIM - 32)
            __stcs(&outb[(OFF32 + gi0) * DVF + oq], scl4(accA, inv[3 * TS + j0]));
        accB = add4(accB, a);
        a = sp[32 * DT];
        accB = add4(accB, a);
        if (gi1 <= L_DIM - 32)
            __stcs(&outb[(OFF32 + gi1) * DVF + oq], scl4(accB, inv[3 * TS + j1]));
    }
}

extern "C" void kernel_launch(void* const* d_in, const int* in_sizes, int n_in,
                              void* d_out, int out_size)
{
    const float* x    = (const float*)d_in[0];
    const int*   mask = (const int*)d_in[1];
    float*       out  = (float*)d_out;

    cudaFuncSetAttribute(msse_kernel,
                         cudaFuncAttributeMaxDynamicSharedMemorySize, SMEM_BYTES);

    msse_kernel<<<GRID, NTH, SMEM_BYTES>>>(x, mask, out);
}